// round 6
// baseline (speedup 1.0000x reference)
#include <cuda_runtime.h>

#define HH 256
#define WW 256
#define BB 8
#define NGT 256
#define NPIX (HH*WW)

static __device__ __constant__ float kMAXD = 362.03867196751236f; // sqrt(256^2+256^2)
#define EPSF 1e-6f

// Persistent scratch (no allocations allowed)
__device__ float g_S[BB*NGT];   // per-(b,j) sum over pixels of (wd+eps)^-9
__device__ float g_t1[BB];      // per-b sum p*min_d
__device__ float g_np[BB];      // per-b sum p

__device__ __forceinline__ float sqrt_approx(float x) {
    float r;
    asm("sqrt.approx.f32 %0, %1;" : "=f"(r) : "f"(x));
    return r;
}
__device__ __forceinline__ float rcp_approx(float x) {
    float r;
    asm("rcp.approx.f32 %0, %1;" : "=f"(r) : "f"(x));
    return r;
}
__device__ __forceinline__ float lg2_approx(float x) {
    float r;
    asm("lg2.approx.f32 %0, %1;" : "=f"(r) : "f"(x));
    return r;
}
__device__ __forceinline__ float ex2_approx(float x) {
    float r;
    asm("ex2.approx.f32 %0, %1;" : "=f"(r) : "f"(x));
    return r;
}

// -------------------------------------------------------------------
__global__ void k_init() {
    int t = threadIdx.x;
#pragma unroll
    for (int i = 0; i < BB; i++) g_S[i*NGT + t] = 0.0f;
    if (t < BB) { g_t1[t] = 0.0f; g_np[t] = 0.0f; }
}

// -------------------------------------------------------------------
// Fused + interleaved kernel. Block = (row, b), 256 threads.
// Thread t plays two roles in ONE loop of 256 iterations:
//   - gt point j=t for term2: iterate pixels i, accumulate (p*d+(1-p)M+eps)^-9
//     (MUFU-bound: 2 MUFU/iter = 16 cyc/SMSP budget)
//   - pixel x=t for term1: iterate gt points i, running min of d^2
//     (3 extra issue slots/iter, hidden under the MUFU shadow)
// Shared data packed as float4 (p_i, c_i, xj_i, dy2_i): one LDS.128 broadcast.
__global__ void __launch_bounds__(256) k_fused(const float* __restrict__ prob,
                                               const float* __restrict__ gt) {
    __shared__ float4 s_d[256];    // (p, (1-p)M+eps, x_j, dy^2+tiny)
    __shared__ float s_c[8], s_p[8];

    const int row = blockIdx.x;
    const int b   = blockIdx.y;
    const int t   = threadIdx.x;

    // gt point j = t
    float2 g  = ((const float2*)gt)[b*NGT + t];   // (y_j, x_j)
    float dy  = (float)row - g.x;
    float dy2e = fmaf(dy, dy, 1e-18f);            // + tiny folds rcp/sqrt(0) guard

    // pixel x = t
    float p = prob[(b*HH + row)*WW + t];
    float c = fmaf(-p, kMAXD, kMAXD) + EPSF;      // (1-p)*M + eps

    s_d[t] = make_float4(p, c, g.y, dy2e);
    __syncthreads();

    float dxA = 0.0f - g.y;        // term2: pixel-x (=i) minus x_j(self); +1/iter
    const float xf = (float)t;     // term1: own pixel x
    float acc = 0.0f;
    float m   = 3.4e38f;

#pragma unroll 8
    for (int i = 0; i < 256; i++) {
        float4 q = s_d[i];                    // one LDS.128 broadcast
        // ---- term2 (thread = gt j, q = pixel i) ----
        float d2 = fmaf(dxA, dxA, dy2e);
        float d  = sqrt_approx(d2);           // MUFU.SQRT
        float tt = fmaf(q.x, d, q.y);         // p*d + (1-p)M + eps
        float iv = rcp_approx(tt);            // MUFU.RCP
        float i2 = iv * iv;
        float i4 = i2 * i2;
        float i8 = i4 * i4;
        acc = fmaf(i8, iv, acc);              // += tt^-9
        dxA += 1.0f;
        // ---- term1 (thread = pixel x, q = gt i) ----
        float dxB = xf - q.z;
        m = fminf(m, fmaf(dxB, dxB, q.w));
    }

    atomicAdd(&g_S[b*NGT + t], acc);

    float cterm = p * sqrt_approx(m);
    float pr = p;
#pragma unroll
    for (int o = 16; o; o >>= 1) {
        cterm += __shfl_down_sync(0xFFFFFFFFu, cterm, o);
        pr    += __shfl_down_sync(0xFFFFFFFFu, pr, o);
    }
    if ((t & 31) == 0) { s_c[t >> 5] = cterm; s_p[t >> 5] = pr; }
    __syncthreads();
    if (t == 0) {
        float C = 0.0f, P = 0.0f;
#pragma unroll
        for (int i = 0; i < 8; i++) { C += s_c[i]; P += s_p[i]; }
        atomicAdd(&g_t1[b], C);
        atomicAdd(&g_np[b], P);
    }
}

// -------------------------------------------------------------------
__global__ void k_final(float* __restrict__ out) {
    __shared__ float sred[8];
    const int t = threadIdx.x;
    const float invA = -1.0f / 9.0f;
    float s = 0.0f;
#pragma unroll
    for (int b = 0; b < BB; b++) {
        float m = g_S[b*NGT + t] * (1.0f / (float)NPIX);
        s += ex2_approx(lg2_approx(m) * invA);   // m^(-1/9), 2x MUFU
    }
#pragma unroll
    for (int o = 16; o; o >>= 1) s += __shfl_down_sync(0xFFFFFFFFu, s, o);
    if ((t & 31) == 0) sred[t >> 5] = s;
    __syncthreads();
    if (t == 0) {
        float T2 = 0.0f;
#pragma unroll
        for (int i = 0; i < 8; i++) T2 += sred[i];
        T2 *= (1.0f / (float)(BB * NGT));
        float T1 = 0.0f;
#pragma unroll
        for (int b = 0; b < BB; b++) T1 += g_t1[b] / (g_np[b] + EPSF);
        T1 *= (1.0f / (float)BB);
        out[0] = T1 + T2;
    }
}

// -------------------------------------------------------------------
extern "C" void kernel_launch(void* const* d_in, const int* in_sizes, int n_in,
                              void* d_out, int out_size) {
    const float* prob = (const float*)d_in[0];   // (B,1,H,W) f32
    const float* gt   = (const float*)d_in[1];   // (B,NGT,2) f32
    float* out = (float*)d_out;

    k_init<<<1, 256>>>();
    dim3 grid(HH, BB);
    k_fused<<<grid, 256>>>(prob, gt);
    k_final<<<1, 256>>>(out);
}

// round 7
// speedup vs baseline: 1.1669x; 1.1669x over previous
#include <cuda_runtime.h>
#include <cstdint>

#define HH 256
#define WW 256
#define BB 8
#define NGT 256
#define NPIX (HH*WW)

static __device__ __constant__ float kMAXD = 362.03867196751236f; // sqrt(256^2+256^2)
#define EPSF 1e-6f

// Persistent scratch (zero at module load; k_final restores zeros after use)
__device__ float g_S[BB*NGT];   // per-(b,j) sum over pixels of (wd+eps)^-9
__device__ float g_t1[BB];      // per-b sum p*min_d
__device__ float g_np[BB];      // per-b sum p

typedef unsigned long long u64;

__device__ __forceinline__ float sqrt_approx(float x) {
    float r; asm("sqrt.approx.f32 %0, %1;" : "=f"(r) : "f"(x)); return r;
}
__device__ __forceinline__ float lg2_approx(float x) {
    float r; asm("lg2.approx.f32 %0, %1;" : "=f"(r) : "f"(x)); return r;
}
__device__ __forceinline__ float ex2_approx(float x) {
    float r; asm("ex2.approx.f32 %0, %1;" : "=f"(r) : "f"(x)); return r;
}
// ---- packed f32x2 helpers (Blackwell FFMA2 path, PTX-only) ----
__device__ __forceinline__ u64 pk2(float x, float y) {
    u64 r; asm("mov.b64 %0, {%1, %2};" : "=l"(r) : "f"(x), "f"(y)); return r;
}
__device__ __forceinline__ float lo2(u64 v) {
    float r; asm("{ .reg .f32 h; mov.b64 {%0, h}, %1; }" : "=f"(r) : "l"(v)); return r;
}
__device__ __forceinline__ float hi2(u64 v) {
    float r; asm("{ .reg .f32 l; mov.b64 {l, %0}, %1; }" : "=f"(r) : "l"(v)); return r;
}
__device__ __forceinline__ u64 ffma2(u64 a, u64 b, u64 c) {
    u64 d; asm("fma.rn.f32x2 %0, %1, %2, %3;" : "=l"(d) : "l"(a), "l"(b), "l"(c)); return d;
}
__device__ __forceinline__ u64 fmul2(u64 a, u64 b) {
    u64 d; asm("mul.rn.f32x2 %0, %1, %2;" : "=l"(d) : "l"(a), "l"(b)); return d;
}
__device__ __forceinline__ u64 fadd2(u64 a, u64 b) {
    u64 d; asm("add.rn.f32x2 %0, %1, %2;" : "=l"(d) : "l"(a), "l"(b)); return d;
}
// bithack reciprocal seed from NEGATIVE input (ntt < 0): bits(tt) = bits(ntt)-0x80000000
// seed = 0x7EF311C3 - bits(tt) = 0xFEF311C3 - bits(ntt)  (mod 2^32)
__device__ __forceinline__ u64 rcp_seed_from_neg(u64 ntt) {
    uint32_t bl = (uint32_t)ntt;
    uint32_t bh = (uint32_t)(ntt >> 32);
    uint32_t sl = 0xFEF311C3u - bl;
    uint32_t sh = 0xFEF311C3u - bh;
    return ((u64)sh << 32) | (u64)sl;
}

// -------------------------------------------------------------------
// Fused, f32x2-packed kernel. Block = (row, b), 256 threads.
// Thread t: gt point j=t (term2) AND pixel x=t (term1).
// Each iteration i handles pixels {2i,2i+1} (term2) and gts {2i,2i+1} (term1).
__global__ void __launch_bounds__(256) k_fused(const float* __restrict__ prob,
                                               const float* __restrict__ gt) {
    __shared__ float4 s_pc[128];   // (-p_{2i}, -p_{2i+1}, -c_{2i}, -c_{2i+1})
    __shared__ float4 s_gt[128];   // (-xj_{2i}, -xj_{2i+1}, dy2e_{2i}, dy2e_{2i+1})
    __shared__ float s_c[8], s_p[8];

    const int row = blockIdx.x;
    const int b   = blockIdx.y;
    const int t   = threadIdx.x;

    // gt point j = t
    float2 g  = ((const float2*)gt)[b*NGT + t];   // (y_j, x_j)
    float dy  = (float)row - g.x;
    float dy2e = fmaf(dy, dy, 1e-18f);

    // pixel x = t
    float p = prob[(b*HH + row)*WW + t];
    float c = fmaf(-p, kMAXD, kMAXD) + EPSF;      // (1-p)*M + eps

    {   // interleaved pair layout, negated where the loop wants negatives
        float* fpc = (float*)s_pc;
        float* fgt = (float*)s_gt;
        int base = (t >> 1) * 4 + (t & 1);
        fpc[base]     = -p;
        fpc[base + 2] = -c;
        fgt[base]     = -g.y;
        fgt[base + 2] = dy2e;
    }
    __syncthreads();

    const u64 one2  = pk2(1.0f, 1.0f);
    const u64 two2  = pk2(2.0f, 2.0f);
    const u64 dy2s  = pk2(dy2e, dy2e);             // term2 self dy^2
    const float xf  = (float)t;
    const u64 xf2   = pk2(xf, xf);

    u64 dxA  = pk2(0.0f - g.y, 1.0f - g.y);        // term2: (x - xj) for x=0,1
    u64 acc2 = pk2(0.0f, 0.0f);
    float mlo = 3.4e38f, mhi = 3.4e38f;

#pragma unroll 4
    for (int i = 0; i < 128; i++) {
        float4 qa = s_pc[i];                       // LDS.128 broadcast
        float4 qb = s_gt[i];                       // LDS.128 broadcast
        // ---- term2 (2 pixels) ----
        u64 d2p = ffma2(dxA, dxA, dy2s);
        u64 dp  = pk2(sqrt_approx(lo2(d2p)), sqrt_approx(hi2(d2p)));  // 2x MUFU
        u64 np2 = pk2(qa.x, qa.y);
        u64 nc2 = pk2(qa.z, qa.w);
        u64 ntt = ffma2(np2, dp, nc2);             // -(p*d + c)
        u64 y0  = rcp_seed_from_neg(ntt);          // ~1/tt, |err|<5%
        u64 e1  = ffma2(ntt, y0, one2);            // 1 - tt*y0
        u64 y1  = ffma2(y0, e1, y0);
        u64 e2  = fmul2(e1, e1);
        u64 y2  = ffma2(y1, e2, y1);               // 1/tt, err ~ d^4
        u64 i2  = fmul2(y2, y2);
        u64 i4  = fmul2(i2, i2);
        u64 i8  = fmul2(i4, i4);
        acc2 = ffma2(i8, y2, acc2);                // += tt^-9
        dxA  = fadd2(dxA, two2);
        // ---- term1 (2 gt points) ----
        u64 nxj2 = pk2(qb.x, qb.y);
        u64 dyg2 = pk2(qb.z, qb.w);
        u64 dxB  = fadd2(xf2, nxj2);               // x - xj
        u64 cand = ffma2(dxB, dxB, dyg2);
        mlo = fminf(mlo, lo2(cand));
        mhi = fminf(mhi, hi2(cand));
    }

    atomicAdd(&g_S[b*NGT + t], lo2(acc2) + hi2(acc2));

    float m = fminf(mlo, mhi);
    float cterm = p * sqrt_approx(m);
    float pr = p;
#pragma unroll
    for (int o = 16; o; o >>= 1) {
        cterm += __shfl_down_sync(0xFFFFFFFFu, cterm, o);
        pr    += __shfl_down_sync(0xFFFFFFFFu, pr, o);
    }
    if ((t & 31) == 0) { s_c[t >> 5] = cterm; s_p[t >> 5] = pr; }
    __syncthreads();
    if (t == 0) {
        float C = 0.0f, P = 0.0f;
#pragma unroll
        for (int i = 0; i < 8; i++) { C += s_c[i]; P += s_p[i]; }
        atomicAdd(&g_t1[b], C);
        atomicAdd(&g_np[b], P);
    }
}

// -------------------------------------------------------------------
// Reduces scratch to the scalar output, then RE-ZEROES the scratch so the
// next graph replay starts from the same state (device globals are zero at
// module load; this maintains the invariant).
__global__ void k_final(float* __restrict__ out) {
    __shared__ float sred[8];
    __shared__ float st1[8];
    const int t = threadIdx.x;
    const float invA = -1.0f / 9.0f;

    float s = 0.0f;
#pragma unroll
    for (int b = 0; b < BB; b++) {
        float m = g_S[b*NGT + t] * (1.0f / (float)NPIX);
        s += ex2_approx(lg2_approx(m) * invA);   // m^(-1/9)
    }
    if (t < BB) st1[t] = g_t1[t] / (g_np[t] + EPSF);

#pragma unroll
    for (int o = 16; o; o >>= 1) s += __shfl_down_sync(0xFFFFFFFFu, s, o);
    if ((t & 31) == 0) sred[t >> 5] = s;
    __syncthreads();

    // re-zero scratch (all reads above are complete for this thread's slots;
    // cross-thread slots were only read by their own threads before the sync)
#pragma unroll
    for (int b = 0; b < BB; b++) g_S[b*NGT + t] = 0.0f;
    if (t < BB) { g_t1[t] = 0.0f; g_np[t] = 0.0f; }

    if (t == 0) {
        float T2 = 0.0f;
#pragma unroll
        for (int i = 0; i < 8; i++) T2 += sred[i];
        T2 *= (1.0f / (float)(BB * NGT));
        float T1 = 0.0f;
#pragma unroll
        for (int b = 0; b < BB; b++) T1 += st1[b];
        T1 *= (1.0f / (float)BB);
        out[0] = T1 + T2;
    }
}

// -------------------------------------------------------------------
extern "C" void kernel_launch(void* const* d_in, const int* in_sizes, int n_in,
                              void* d_out, int out_size) {
    const float* prob = (const float*)d_in[0];   // (B,1,H,W) f32
    const float* gt   = (const float*)d_in[1];   // (B,NGT,2) f32
    float* out = (float*)d_out;

    dim3 grid(HH, BB);
    k_fused<<<grid, 256>>>(prob, gt);
    k_final<<<1, 256>>>(out);
}

// round 10
// speedup vs baseline: 1.1673x; 1.0004x over previous
#include <cuda_runtime.h>
#include <cstdint>

#define HH 256
#define WW 256
#define BB 8
#define NGT 256
#define NPIX (HH*WW)
#define NBLK (HH*BB)

static __device__ __constant__ float kMAXD = 362.03867196751236f; // sqrt(256^2+256^2)
#define EPSF 1e-6f

// Persistent scratch (zero at module load; finalize restores zeros after use)
__device__ float g_S[BB*NGT];   // per-(b,j) sum over pixels of (wd+eps)^-9
__device__ float g_t1[BB];      // per-b sum p*min_d
__device__ float g_np[BB];      // per-b sum p
__device__ unsigned int g_done; // block-completion ticket

typedef unsigned long long u64;

__device__ __forceinline__ float sqrt_approx(float x) {
    float r; asm("sqrt.approx.f32 %0, %1;" : "=f"(r) : "f"(x)); return r;
}
__device__ __forceinline__ float lg2_approx(float x) {
    float r; asm("lg2.approx.f32 %0, %1;" : "=f"(r) : "f"(x)); return r;
}
__device__ __forceinline__ float ex2_approx(float x) {
    float r; asm("ex2.approx.f32 %0, %1;" : "=f"(r) : "f"(x)); return r;
}
// ---- packed f32x2 helpers (Blackwell FFMA2 path, PTX-only) ----
__device__ __forceinline__ u64 pk2(float x, float y) {
    u64 r; asm("mov.b64 %0, {%1, %2};" : "=l"(r) : "f"(x), "f"(y)); return r;
}
__device__ __forceinline__ float lo2(u64 v) {
    float r; asm("{ .reg .f32 h; mov.b64 {%0, h}, %1; }" : "=f"(r) : "l"(v)); return r;
}
__device__ __forceinline__ float hi2(u64 v) {
    float r; asm("{ .reg .f32 l; mov.b64 {l, %0}, %1; }" : "=f"(r) : "l"(v)); return r;
}
__device__ __forceinline__ u64 ffma2(u64 a, u64 b, u64 c) {
    u64 d; asm("fma.rn.f32x2 %0, %1, %2, %3;" : "=l"(d) : "l"(a), "l"(b), "l"(c)); return d;
}
__device__ __forceinline__ u64 fmul2(u64 a, u64 b) {
    u64 d; asm("mul.rn.f32x2 %0, %1, %2;" : "=l"(d) : "l"(a), "l"(b)); return d;
}
__device__ __forceinline__ u64 fadd2(u64 a, u64 b) {
    u64 d; asm("add.rn.f32x2 %0, %1, %2;" : "=l"(d) : "l"(a), "l"(b)); return d;
}
// bithack reciprocal seed from NEGATIVE input (ntt < 0):
// seed = 0x7EF311C3 - bits(tt) = 0xFEF311C3 - bits(ntt)  (mod 2^32), per 32-bit half
__device__ __forceinline__ u64 rcp_seed_from_neg(u64 ntt) {
    uint32_t bl = (uint32_t)ntt;
    uint32_t bh = (uint32_t)(ntt >> 32);
    uint32_t sl = 0xFEF311C3u - bl;
    uint32_t sh = 0xFEF311C3u - bh;
    return ((u64)sh << 32) | (u64)sl;
}

// -------------------------------------------------------------------
// Single fused kernel. Block = (row, b), 256 threads.
// Thread t: gt point j=t (term2) AND pixel x=t (term1), one interleaved loop,
// 2 pixels / 2 gt points per iteration in packed f32x2.
// The LAST block to finish (ticket) performs the final reduction to out[0]
// and re-zeroes all scratch for the next graph replay.
__global__ void __launch_bounds__(256) k_fused(const float* __restrict__ prob,
                                               const float* __restrict__ gt,
                                               float* __restrict__ out) {
    __shared__ ulonglong2 s_a[128];  // .x = (-p_{2i},-p_{2i+1})  .y = (-c_{2i},-c_{2i+1})
    __shared__ ulonglong2 s_b[128];  // .x = (-xj_{2i},-xj_{2i+1}) .y = (dy2e_{2i},dy2e_{2i+1})
    __shared__ float s_c[8], s_p[8];
    __shared__ unsigned int s_last;

    const int row = blockIdx.x;
    const int b   = blockIdx.y;
    const int t   = threadIdx.x;

    // gt point j = t
    float2 g  = ((const float2*)gt)[b*NGT + t];   // (y_j, x_j)
    float dy  = (float)row - g.x;
    float dy2e = fmaf(dy, dy, 1e-18f);

    // pixel x = t
    float p = prob[(b*HH + row)*WW + t];
    float c = fmaf(-p, kMAXD, kMAXD) + EPSF;      // (1-p)*M + eps

    {   // interleaved pair layout, negated where the loop wants negatives
        float* fa = (float*)s_a;
        float* fb = (float*)s_b;
        int base = (t >> 1) * 4 + (t & 1);
        fa[base]     = -p;
        fa[base + 2] = -c;
        fb[base]     = -g.y;
        fb[base + 2] = dy2e;
    }
    __syncthreads();

    const u64 one2  = pk2(1.0f, 1.0f);
    const u64 two2  = pk2(2.0f, 2.0f);
    const u64 dy2s  = pk2(dy2e, dy2e);             // term2 self dy^2
    const float xf  = (float)t;
    const u64 xf2   = pk2(xf, xf);

    u64 dxA  = pk2(0.0f - g.y, 1.0f - g.y);        // term2: (x - xj) for x=0,1
    u64 acc2 = pk2(0.0f, 0.0f);
    float mlo = 3.4e38f, mhi = 3.4e38f;

#pragma unroll 4
    for (int i = 0; i < 128; i++) {
        ulonglong2 qa = s_a[i];                    // LDS.128 -> two aligned f32x2 pairs
        ulonglong2 qb = s_b[i];                    // LDS.128
        // ---- term2 (2 pixels) ----
        u64 d2p = ffma2(dxA, dxA, dy2s);
        u64 dp  = pk2(sqrt_approx(lo2(d2p)), sqrt_approx(hi2(d2p)));  // 2x MUFU
        u64 ntt = ffma2(qa.x, dp, qa.y);           // -(p*d + c)
        u64 y0  = rcp_seed_from_neg(ntt);          // ~1/tt, |err|<5% (2x IADD, ALU pipe)
        u64 e1  = ffma2(ntt, y0, one2);            // 1 - tt*y0
        u64 y1  = ffma2(y0, e1, y0);
        u64 e2  = fmul2(e1, e1);
        u64 y2  = ffma2(y1, e2, y1);               // 1/tt, err ~ d^4
        u64 i2  = fmul2(y2, y2);
        u64 i4  = fmul2(i2, i2);
        u64 i8  = fmul2(i4, i4);
        acc2 = ffma2(i8, y2, acc2);                // += tt^-9
        dxA  = fadd2(dxA, two2);
        // ---- term1 (2 gt points) ----
        u64 dxB  = fadd2(xf2, qb.x);               // x - xj
        u64 cand = ffma2(dxB, dxB, qb.y);
        mlo = fminf(mlo, lo2(cand));
        mhi = fminf(mhi, hi2(cand));
    }

    atomicAdd(&g_S[b*NGT + t], lo2(acc2) + hi2(acc2));

    float m = fminf(mlo, mhi);
    float cterm = p * sqrt_approx(m);
    float pr = p;
#pragma unroll
    for (int o = 16; o; o >>= 1) {
        cterm += __shfl_down_sync(0xFFFFFFFFu, cterm, o);
        pr    += __shfl_down_sync(0xFFFFFFFFu, pr, o);
    }
    if ((t & 31) == 0) { s_c[t >> 5] = cterm; s_p[t >> 5] = pr; }
    __syncthreads();
    if (t == 0) {
        float C = 0.0f, P = 0.0f;
#pragma unroll
        for (int i = 0; i < 8; i++) { C += s_c[i]; P += s_p[i]; }
        atomicAdd(&g_t1[b], C);
        atomicAdd(&g_np[b], P);
    }

    // ---- completion ticket: release this block's atomics, grab ticket ----
    __threadfence();                 // every thread releases its global atomics
    __syncthreads();                 // all fences done before the ticket bump
    if (t == 0) {
        s_last = (atomicAdd(&g_done, 1u) == (NBLK - 1)) ? 1u : 0u;
    }
    __syncthreads();
    if (s_last == 0u) return;

    // ---- finalize (only the last block) ----
    __threadfence();                 // acquire: all other blocks' atomics visible
    __shared__ float sred[8];
    __shared__ float st1[8];
    const float invA = -1.0f / 9.0f;

    float s = 0.0f;
#pragma unroll
    for (int bb = 0; bb < BB; bb++) {
        float mm = __ldcg(&g_S[bb*NGT + t]) * (1.0f / (float)NPIX);
        s += ex2_approx(lg2_approx(mm) * invA);   // mm^(-1/9)
    }
    if (t < BB) st1[t] = __ldcg(&g_t1[t]) / (__ldcg(&g_np[t]) + EPSF);

#pragma unroll
    for (int o = 16; o; o >>= 1) s += __shfl_down_sync(0xFFFFFFFFu, s, o);
    if ((t & 31) == 0) sred[t >> 5] = s;
    __syncthreads();

    // re-zero scratch + ticket for the next graph replay
#pragma unroll
    for (int bb = 0; bb < BB; bb++) g_S[bb*NGT + t] = 0.0f;
    if (t < BB) { g_t1[t] = 0.0f; g_np[t] = 0.0f; }
    if (t == 0) g_done = 0u;

    if (t == 0) {
        float T2 = 0.0f;
#pragma unroll
        for (int i = 0; i < 8; i++) T2 += sred[i];
        T2 *= (1.0f / (float)(BB * NGT));
        float T1 = 0.0f;
#pragma unroll
        for (int bb = 0; bb < BB; bb++) T1 += st1[bb];
        T1 *= (1.0f / (float)BB);
        out[0] = T1 + T2;
    }
}

// -------------------------------------------------------------------
extern "C" void kernel_launch(void* const* d_in, const int* in_sizes, int n_in,
                              void* d_out, int out_size) {
    const float* prob = (const float*)d_in[0];   // (B,1,H,W) f32
    const float* gt   = (const float*)d_in[1];   // (B,NGT,2) f32
    float* out = (float*)d_out;

    dim3 grid(HH, BB);
    k_fused<<<grid, 256>>>(prob, gt, out);
}